// round 13
// baseline (speedup 1.0000x reference)
#include <cuda_runtime.h>
#include <cuda_fp16.h>
#include <math.h>
#include <stdint.h>

// NT-Xent loss on GB300, f16-acc HMMA + symmetry + occ-3 2-stage pipeline
// (R12) + mixed-granularity grid: pairs 0..1775 as full 128x128 tiles
// (exactly 4 waves of 444 slots), the remaining 304 pairs split into 4
// column-quarter tiles (128x32) that backfill the former 5th wave.
// Quarter col sums are complete -> g_rs directly; quarter row sums are
// partial -> g_rq scratch, folded in by the loss kernel (no atomics,
// deterministic). All positive pairs live in full tiles (id(b,b+32)<1776).

#define NROWS 8192
#define NC    512
#define BHALF 4096
#define NB    (NROWS / 128)         // 64
#define NPAIRS 2080
#define FULLPAIRS 1776              // 444 slots * 4 waves
#define REMPAIRS (NPAIRS - FULLPAIRS)   // 304
#define GRID (FULLPAIRS + REMPAIRS * 4) // 2992

#define BM 128
#define BN 128
#define BK 64
#define KITERS (NC / BK)        // 8
#define NSTAGE 2
#define STAGE_BYTES (2 * BM * BK * 2)   // A + B = 32768
#define SMEM_TOTAL (NSTAGE * STAGE_BYTES)  // 65536

__device__ __align__(1024) __half g_zn[(size_t)NROWS * NC];
__device__ float g_pos[BHALF];
__device__ float g_rs[(size_t)NROWS * NB];
__device__ float g_rq[(size_t)REMPAIRS * 4 * 128];  // quarter row partials
__device__ float g_part[64];
__device__ int g_cnt;   // zero-initialized; self-resetting each run

__device__ __forceinline__ uint32_t smem_u32(const void* p) {
    uint32_t a;
    asm("{ .reg .u64 t; cvta.to.shared.u64 t, %1; cvt.u32.u64 %0, t; }"
        : "=r"(a) : "l"(p));
    return a;
}

#define CP_ASYNC16(dst, src) \
    asm volatile("cp.async.cg.shared.global [%0], [%1], 16;" :: "r"(dst), "l"(src) : "memory")
#define CP_COMMIT() asm volatile("cp.async.commit_group;" ::: "memory")

#define LDSM_X4(r0, r1, r2, r3, addr)                                          \
    asm volatile("ldmatrix.sync.aligned.m8n8.x4.shared.b16 {%0,%1,%2,%3}, [%4];" \
                 : "=r"(r0), "=r"(r1), "=r"(r2), "=r"(r3) : "r"(addr))
#define LDSM_X2(r0, r1, addr)                                                  \
    asm volatile("ldmatrix.sync.aligned.m8n8.x2.shared.b16 {%0,%1}, [%2];"     \
                 : "=r"(r0), "=r"(r1) : "r"(addr))

#define MMAF16(c, a0, a1, a2, a3, b0, b1)                                      \
    asm volatile("mma.sync.aligned.m16n8k16.row.col.f16.f16.f16.f16 "          \
                 "{%0,%1},{%2,%3,%4,%5},{%6,%7},{%0,%1};"                      \
                 : "+r"((c)[0]), "+r"((c)[1])                                  \
                 : "r"(a0), "r"(a1), "r"(a2), "r"(a3), "r"(b0), "r"(b1))

// ---------------------------------------------------------------------------
// Kernel 1: L2-normalize rows, emit fp16 z (identical to R12)
// ---------------------------------------------------------------------------
__global__ __launch_bounds__(512) void normalize_kernel(
        const float* __restrict__ z1, const float* __restrict__ z2) {
    const int lane = threadIdx.x & 31;
    const int r = blockIdx.x * 16 + (threadIdx.x >> 5);
    const float* row = (r < BHALF) ? (z1 + (size_t)r * NC)
                                   : (z2 + (size_t)(r - BHALF) * NC);
    float4 v[4];
#pragma unroll
    for (int i = 0; i < 4; i++) v[i] = ((const float4*)row)[lane + 32 * i];
    float s = 0.f;
#pragma unroll
    for (int i = 0; i < 4; i++)
        s += v[i].x * v[i].x + v[i].y * v[i].y + v[i].z * v[i].z + v[i].w * v[i].w;
#pragma unroll
    for (int o = 16; o; o >>= 1) s += __shfl_xor_sync(0xFFFFFFFFu, s, o);
    float inv = 1.0f / fmaxf(sqrtf(s), 1e-12f);
    uint2* dst = (uint2*)(g_zn + (size_t)r * NC);
#pragma unroll
    for (int i = 0; i < 4; i++) {
        uint2 out;
        ((__half2*)&out)[0] = __floats2half2_rn(v[i].x * inv, v[i].y * inv);
        ((__half2*)&out)[1] = __floats2half2_rn(v[i].z * inv, v[i].w * inv);
        dst[lane + 32 * i] = out;
    }
}

// ---------------------------------------------------------------------------
// Kernel 2: fused GEMM + exp + row/col sums + positive capture.
// bid < 1776: full 128x128 pair tile (R12 path, unchanged).
// bid >= 1776: column-quarter tile (128x32) of remainder pair.
// ---------------------------------------------------------------------------
__global__ __launch_bounds__(256, 3) void gemm_kernel() {
    extern __shared__ __align__(1024) char smem[];
    const int tid = threadIdx.x;
    const int lane = tid & 31;
    const int w = tid >> 5;
    const int wm = w >> 2;       // 0..1
    const int wn = w & 3;        // 0..3

    const int bid = blockIdx.x;
    const bool isQ = (bid >= FULLPAIRS);
    int pairId, q;
    if (!isQ) { pairId = bid; q = 0; }
    else { pairId = FULLPAIRS + ((bid - FULLPAIRS) >> 2); q = (bid - FULLPAIRS) & 3; }

    int rem = pairId;
    int bm = 0;
#pragma unroll 1
    while (rem >= (NB - bm)) { rem -= (NB - bm); bm++; }
    const int bn = bm + rem;
    const int r0 = bm * BM;
    const int cB = bn * BN + q * 32;       // B loader col base (q=0 for full)
    const uint32_t sbase = smem_u32(smem);

    // ---- cp.async: threads 0..127 -> A rows, 128..255 -> B rows ----
    const int half = tid >> 7;
    const int lrow = tid & 127;
    const int rowlim = isQ ? 32 : 128;
    const bool ldok = (half == 0) || (lrow < rowlim);
    const char* grow = (const char*)g_zn +
        ((size_t)((half ? cB : r0) + lrow)) * (NC * 2);
    const uint32_t sdst = sbase + (uint32_t)half * (BM * BK * 2) +
                          (uint32_t)lrow * 128u;
    const uint32_t xr = ((uint32_t)lrow & 7u) << 4;

#define ISSUE_STAGE(s_)                                                        \
    do {                                                                       \
        if (ldok) {                                                            \
            const char* g_ = grow + (s_) * (BK * 2);                           \
            uint32_t d_ = sdst + (uint32_t)((s_) & 1) * STAGE_BYTES;           \
            _Pragma("unroll")                                                  \
            for (int c_ = 0; c_ < 8; c_++)                                     \
                CP_ASYNC16(d_ + (((uint32_t)c_ * 16u) ^ xr), g_ + c_ * 16);    \
        }                                                                      \
        CP_COMMIT();                                                           \
    } while (0)

    ISSUE_STAGE(0);

    // shared addressing pieces
    const uint32_t xA = ((uint32_t)(lane & 7)) << 4;
    const uint32_t chunkA = ((uint32_t)(lane >> 4)) * 16u;
    const uint32_t aBase = sbase + (uint32_t)(wm * 64 + (lane & 15)) * 128u;
    float* redr = (float*)smem;          // [4 wn][128 rows]
    float* redc = (float*)smem + 512;    // [2 wm][<=128 cols]

    if (!isQ) {
        // ===================== FULL 128x128 path (R12) =====================
        const uint32_t xB = xA;
        const uint32_t chunkB = ((uint32_t)((lane >> 3) & 1)) * 16u;
        const uint32_t bBase = sbase + (uint32_t)(BM * BK * 2) +
            (uint32_t)(wn * 32 + ((lane >> 4) & 1) * 8 + (lane & 7)) * 128u;

        uint32_t acc[4][4][2];
#pragma unroll
        for (int mi = 0; mi < 4; mi++)
#pragma unroll
            for (int ni = 0; ni < 4; ni++) {
                acc[mi][ni][0] = 0u;
                acc[mi][ni][1] = 0u;
            }

#pragma unroll 1
        for (int i = 0; i < KITERS; i++) {
            asm volatile("cp.async.wait_group 0;" ::: "memory");
            __syncthreads();
            if (i + 1 < KITERS) ISSUE_STAGE(i + 1);

            const uint32_t sb = (uint32_t)(i & 1) * STAGE_BYTES;
#pragma unroll
            for (int kk = 0; kk < 4; kk++) {
                const uint32_t kkb = (uint32_t)kk * 32u;
                const uint32_t offA = sb + ((kkb | chunkA) ^ xA);
                const uint32_t offB = sb + ((kkb | chunkB) ^ xB);
                uint32_t a[4][4], b[2][4];
#pragma unroll
                for (int mi = 0; mi < 4; mi++)
                    LDSM_X4(a[mi][0], a[mi][1], a[mi][2], a[mi][3],
                            aBase + (uint32_t)(mi * 2048) + offA);
#pragma unroll
                for (int np = 0; np < 2; np++)
                    LDSM_X4(b[np][0], b[np][1], b[np][2], b[np][3],
                            bBase + (uint32_t)(np * 2048) + offB);
#pragma unroll
                for (int mi = 0; mi < 4; mi++)
#pragma unroll
                    for (int ni = 0; ni < 4; ni++)
                        MMAF16(acc[mi][ni],
                               a[mi][0], a[mi][1], a[mi][2], a[mi][3],
                               b[ni >> 1][(ni & 1) * 2],
                               b[ni >> 1][(ni & 1) * 2 + 1]);
            }
        }

        float vr[4][2], cv[4][2];
#pragma unroll
        for (int i = 0; i < 4; i++) {
            vr[i][0] = vr[i][1] = 0.f;
            cv[i][0] = cv[i][1] = 0.f;
        }
#pragma unroll
        for (int mi = 0; mi < 4; mi++)
#pragma unroll
            for (int ni = 0; ni < 4; ni++)
#pragma unroll
                for (int h = 0; h < 2; h++) {
                    float2 f = __half22float2(*(__half2*)&acc[mi][ni][h]);
                    int rowg = r0 + wm * 64 + mi * 16 + h * 8 + (lane >> 2);
                    int colb = bn * BN + wn * 32 + ni * 8 + (lane & 3) * 2;
                    float v0 = __expf(f.x * 10.0f);
                    float v1 = __expf(f.y * 10.0f);
                    vr[mi][h] += v0 + v1;
                    cv[ni][0] += v0;
                    cv[ni][1] += v1;
                    if (colb == rowg + BHALF) g_pos[rowg] = v0;
                    if (colb + 1 == rowg + BHALF) g_pos[rowg] = v1;
                }
#pragma unroll
        for (int mi = 0; mi < 4; mi++)
#pragma unroll
            for (int h = 0; h < 2; h++) {
                float v = vr[mi][h];
                v += __shfl_xor_sync(0xFFFFFFFFu, v, 1);
                v += __shfl_xor_sync(0xFFFFFFFFu, v, 2);
                vr[mi][h] = v;
            }
#pragma unroll
        for (int ni = 0; ni < 4; ni++)
#pragma unroll
            for (int b = 0; b < 2; b++) {
                float v = cv[ni][b];
                v += __shfl_xor_sync(0xFFFFFFFFu, v, 4);
                v += __shfl_xor_sync(0xFFFFFFFFu, v, 8);
                v += __shfl_xor_sync(0xFFFFFFFFu, v, 16);
                cv[ni][b] = v;
            }

        __syncthreads();
        if ((lane & 3) == 0) {
#pragma unroll
            for (int mi = 0; mi < 4; mi++)
#pragma unroll
                for (int h = 0; h < 2; h++)
                    redr[wn * 128 + wm * 64 + mi * 16 + h * 8 + (lane >> 2)] = vr[mi][h];
        }
        if (lane < 4) {
#pragma unroll
            for (int ni = 0; ni < 4; ni++)
#pragma unroll
                for (int b = 0; b < 2; b++)
                    redc[wm * 128 + wn * 32 + ni * 8 + lane * 2 + b] = cv[ni][b];
        }
        __syncthreads();
        if (tid < 128) {
            float t = redr[tid] + redr[128 + tid] + redr[256 + tid] + redr[384 + tid];
            g_rs[((size_t)(r0 + tid)) * NB + bn] = t;
        } else if (bm != bn) {
            int t2 = tid - 128;
            float t = redc[t2] + redc[128 + t2];
            g_rs[((size_t)(bn * BN + t2)) * NB + bm] = t;
        }
    } else {
        // ===================== QUARTER 128x32 path =====================
        const uint32_t chunkB2 = ((uint32_t)((lane >> 3) & 1)) * 16u;
        const uint32_t bBaseq = sbase + (uint32_t)(BM * BK * 2) +
            (uint32_t)(wn * 8 + (lane & 7)) * 128u;

        uint32_t acc2[4][2];
#pragma unroll
        for (int mi = 0; mi < 4; mi++) { acc2[mi][0] = 0u; acc2[mi][1] = 0u; }

#pragma unroll 1
        for (int i = 0; i < KITERS; i++) {
            asm volatile("cp.async.wait_group 0;" ::: "memory");
            __syncthreads();
            if (i + 1 < KITERS) ISSUE_STAGE(i + 1);

            const uint32_t sb = (uint32_t)(i & 1) * STAGE_BYTES;
#pragma unroll
            for (int kk = 0; kk < 4; kk++) {
                const uint32_t kkb = (uint32_t)kk * 32u;
                const uint32_t offA = sb + ((kkb | chunkA) ^ xA);
                uint32_t b0, b1;
                LDSM_X2(b0, b1, bBaseq + sb + ((kkb | chunkB2) ^ xA));
#pragma unroll
                for (int mi = 0; mi < 4; mi++) {
                    uint32_t a0, a1, a2, a3;
                    LDSM_X4(a0, a1, a2, a3,
                            aBase + (uint32_t)(mi * 2048) + offA);
                    MMAF16(acc2[mi], a0, a1, a2, a3, b0, b1);
                }
            }
        }

        // epilogue: no positive capture needed (all positives in full tiles)
        float vr[4][2];
        float cvq[2] = {0.f, 0.f};
#pragma unroll
        for (int mi = 0; mi < 4; mi++) {
#pragma unroll
            for (int h = 0; h < 2; h++) {
                float2 f = __half22float2(*(__half2*)&acc2[mi][h]);
                float v0 = __expf(f.x * 10.0f);
                float v1 = __expf(f.y * 10.0f);
                vr[mi][h] = v0 + v1;
                cvq[0] += v0;
                cvq[1] += v1;
            }
        }
#pragma unroll
        for (int mi = 0; mi < 4; mi++)
#pragma unroll
            for (int h = 0; h < 2; h++) {
                float v = vr[mi][h];
                v += __shfl_xor_sync(0xFFFFFFFFu, v, 1);
                v += __shfl_xor_sync(0xFFFFFFFFu, v, 2);
                vr[mi][h] = v;
            }
#pragma unroll
        for (int b = 0; b < 2; b++) {
            float v = cvq[b];
            v += __shfl_xor_sync(0xFFFFFFFFu, v, 4);
            v += __shfl_xor_sync(0xFFFFFFFFu, v, 8);
            v += __shfl_xor_sync(0xFFFFFFFFu, v, 16);
            cvq[b] = v;
        }

        __syncthreads();
        if ((lane & 3) == 0) {
#pragma unroll
            for (int mi = 0; mi < 4; mi++)
#pragma unroll
                for (int h = 0; h < 2; h++)
                    redr[wn * 128 + wm * 64 + mi * 16 + h * 8 + (lane >> 2)] = vr[mi][h];
        }
        if (lane < 4) {
#pragma unroll
            for (int b = 0; b < 2; b++)
                redc[wm * 32 + wn * 8 + lane * 2 + b] = cvq[b];
        }
        __syncthreads();
        const int pl = pairId - FULLPAIRS;
        if (tid < 128) {
            float t = redr[tid] + redr[128 + tid] + redr[256 + tid] + redr[384 + tid];
            g_rq[((size_t)(pl * 4 + q)) * 128 + tid] = t;
        } else if (tid < 160 && bm != bn) {
            int t2 = tid - 128;
            float t = redc[t2] + redc[32 + t2];
            g_rs[((size_t)(cB + t2)) * NB + bm] = t;
        }
    }
}

// ---------------------------------------------------------------------------
// Kernel 3: per-128-row partial loss sums (with quarter-scratch fold);
// last block finalizes the scalar.
// ---------------------------------------------------------------------------
__global__ void loss_kernel(float* __restrict__ out) {
    int r = blockIdx.x * 128 + threadIdx.x;
    const float4* p4 = (const float4*)&g_rs[(size_t)r * NB];
    float tot = 0.f;
#pragma unroll
    for (int i = 0; i < NB / 4; i++) {
        float4 q = p4[i];
        tot += (q.x + q.y) + (q.z + q.w);
    }
    // fold remainder-pair row partials from scratch
    {
        int B = r >> 7;
        int startB = 64 * B - (B * (B - 1)) / 2;
        int bnmin = FULLPAIRS - startB + B;
        if (bnmin < B) bnmin = B;
        for (int bn = bnmin; bn < NB; bn++) {
            int pl = startB + bn - B - FULLPAIRS;
            const float* pq = &g_rq[(size_t)pl * 512 + (r & 127)];
            tot += (pq[0] + pq[128]) + (pq[256] + pq[384]);
        }
    }
    float p = g_pos[r & (BHALF - 1)];
    float s = logf(tot - p) - logf(p);
#pragma unroll
    for (int o = 16; o; o >>= 1) s += __shfl_xor_sync(0xFFFFFFFFu, s, o);
    __shared__ float ws[4];
    __shared__ int is_last;
    if ((threadIdx.x & 31) == 0) ws[threadIdx.x >> 5] = s;
    __syncthreads();
    if (threadIdx.x == 0) {
        g_part[blockIdx.x] = ws[0] + ws[1] + ws[2] + ws[3];
        __threadfence();
        is_last = (atomicAdd(&g_cnt, 1) == 63) ? 1 : 0;
        if (is_last) g_cnt = 0;   // reset for next graph replay
    }
    __syncthreads();
    if (is_last && threadIdx.x < 64) {
        float v = g_part[threadIdx.x];
#pragma unroll
        for (int o = 16; o; o >>= 1) v += __shfl_xor_sync(0xFFFFFFFFu, v, o);
        __shared__ float h2[2];
        if ((threadIdx.x & 31) == 0) h2[threadIdx.x >> 5] = v;
        __syncwarp();
        __syncthreads();
        if (threadIdx.x == 0)
            out[0] = (h2[0] + h2[1]) / ((float)NROWS * (float)BHALF);
    }
}

extern "C" void kernel_launch(void* const* d_in, const int* in_sizes, int n_in,
                              void* d_out, int out_size) {
    const float* z1 = (const float*)d_in[0];
    const float* z2 = (const float*)d_in[1];
    (void)in_sizes; (void)n_in; (void)out_size;

    cudaFuncSetAttribute(gemm_kernel, cudaFuncAttributeMaxDynamicSharedMemorySize,
                         SMEM_TOTAL);

    normalize_kernel<<<NROWS / 16, 512>>>(z1, z2);
    gemm_kernel<<<GRID, 256, SMEM_TOTAL>>>();
    loss_kernel<<<64, 128>>>((float*)d_out);
}

// round 14
// speedup vs baseline: 1.2583x; 1.2583x over previous
#include <cuda_runtime.h>
#include <cuda_fp16.h>
#include <math.h>
#include <stdint.h>

// NT-Xent loss on GB300, f16-acc HMMA + symmetry + occ-3 2-stage pipeline.
// R14: R12 skeleton with 64x64 warp tiles (4 warps / 128 threads per CTA):
// 8 LDSM per 32 MMA instead of 6 per 16 -> 33% lower LSU pressure, 2x
// fragment reuse. Grid/pipeline/normalize/loss identical to the 176us R12.

#define NROWS 8192
#define NC    512
#define BHALF 4096
#define NB    (NROWS / 128)         // 64
#define NPAIRS (NB * (NB + 1) / 2)  // 2080

#define BM 128
#define BN 128
#define BK 64
#define KITERS (NC / BK)        // 8
#define NSTAGE 2
#define STAGE_BYTES (2 * BM * BK * 2)   // A + B = 32768
#define SMEM_TOTAL (NSTAGE * STAGE_BYTES)  // 65536

__device__ __align__(1024) __half g_zn[(size_t)NROWS * NC];
__device__ float g_pos[BHALF];
__device__ float g_rs[(size_t)NROWS * NB];
__device__ float g_part[64];
__device__ int g_cnt;   // zero-initialized; self-resetting each run

__device__ __forceinline__ uint32_t smem_u32(const void* p) {
    uint32_t a;
    asm("{ .reg .u64 t; cvta.to.shared.u64 t, %1; cvt.u32.u64 %0, t; }"
        : "=r"(a) : "l"(p));
    return a;
}

#define CP_ASYNC16(dst, src) \
    asm volatile("cp.async.cg.shared.global [%0], [%1], 16;" :: "r"(dst), "l"(src) : "memory")
#define CP_COMMIT() asm volatile("cp.async.commit_group;" ::: "memory")

#define LDSM_X4(r0, r1, r2, r3, addr)                                          \
    asm volatile("ldmatrix.sync.aligned.m8n8.x4.shared.b16 {%0,%1,%2,%3}, [%4];" \
                 : "=r"(r0), "=r"(r1), "=r"(r2), "=r"(r3) : "r"(addr))

#define MMAF16(c, a0, a1, a2, a3, b0, b1)                                      \
    asm volatile("mma.sync.aligned.m16n8k16.row.col.f16.f16.f16.f16 "          \
                 "{%0,%1},{%2,%3,%4,%5},{%6,%7},{%0,%1};"                      \
                 : "+r"((c)[0]), "+r"((c)[1])                                  \
                 : "r"(a0), "r"(a1), "r"(a2), "r"(a3), "r"(b0), "r"(b1))

// ---------------------------------------------------------------------------
// Kernel 1: L2-normalize rows, emit fp16 z (identical to R12)
// ---------------------------------------------------------------------------
__global__ __launch_bounds__(512) void normalize_kernel(
        const float* __restrict__ z1, const float* __restrict__ z2) {
    const int lane = threadIdx.x & 31;
    const int r = blockIdx.x * 16 + (threadIdx.x >> 5);
    const float* row = (r < BHALF) ? (z1 + (size_t)r * NC)
                                   : (z2 + (size_t)(r - BHALF) * NC);
    float4 v[4];
#pragma unroll
    for (int i = 0; i < 4; i++) v[i] = ((const float4*)row)[lane + 32 * i];
    float s = 0.f;
#pragma unroll
    for (int i = 0; i < 4; i++)
        s += v[i].x * v[i].x + v[i].y * v[i].y + v[i].z * v[i].z + v[i].w * v[i].w;
#pragma unroll
    for (int o = 16; o; o >>= 1) s += __shfl_xor_sync(0xFFFFFFFFu, s, o);
    float inv = 1.0f / fmaxf(sqrtf(s), 1e-12f);
    uint2* dst = (uint2*)(g_zn + (size_t)r * NC);
#pragma unroll
    for (int i = 0; i < 4; i++) {
        uint2 out;
        ((__half2*)&out)[0] = __floats2half2_rn(v[i].x * inv, v[i].y * inv);
        ((__half2*)&out)[1] = __floats2half2_rn(v[i].z * inv, v[i].w * inv);
        dst[lane + 32 * i] = out;
    }
}

// ---------------------------------------------------------------------------
// Kernel 2: fused GEMM + exp + row/col sums + positive capture (upper tri).
// 128 threads = 4 warps in 2(M) x 2(N); warp tile 64x64 via m16n8k16.
// 2-stage pipeline, occupancy 3.
// ---------------------------------------------------------------------------
__global__ __launch_bounds__(128, 3) void gemm_kernel() {
    extern __shared__ __align__(1024) char smem[];
    const int tid = threadIdx.x;
    const int lane = tid & 31;
    const int w = tid >> 5;
    const int wm = w >> 1;       // 0..1
    const int wn = w & 1;        // 0..1

    int rem = blockIdx.x;
    int bm = 0;
#pragma unroll 1
    while (rem >= (NB - bm)) { rem -= (NB - bm); bm++; }
    const int bn = bm + rem;
    const int r0 = bm * BM;
    const int c0 = bn * BN;
    const uint32_t sbase = smem_u32(smem);

    // ---- cp.async: 128 threads; thread t loads A row t AND B row t ----
    const char* growA = (const char*)g_zn + ((size_t)(r0 + tid)) * (NC * 2);
    const char* growB = (const char*)g_zn + ((size_t)(c0 + tid)) * (NC * 2);
    const uint32_t sdstA = sbase + (uint32_t)tid * 128u;
    const uint32_t sdstB = sbase + (uint32_t)(BM * BK * 2) + (uint32_t)tid * 128u;
    const uint32_t xr = ((uint32_t)tid & 7u) << 4;

#define ISSUE_STAGE(s_)                                                        \
    do {                                                                       \
        const char* gA_ = growA + (s_) * (BK * 2);                             \
        const char* gB_ = growB + (s_) * (BK * 2);                             \
        uint32_t dA_ = sdstA + (uint32_t)((s_) & 1) * STAGE_BYTES;             \
        uint32_t dB_ = sdstB + (uint32_t)((s_) & 1) * STAGE_BYTES;             \
        _Pragma("unroll")                                                      \
        for (int c_ = 0; c_ < 8; c_++) {                                       \
            CP_ASYNC16(dA_ + (((uint32_t)c_ * 16u) ^ xr), gA_ + c_ * 16);      \
            CP_ASYNC16(dB_ + (((uint32_t)c_ * 16u) ^ xr), gB_ + c_ * 16);      \
        }                                                                      \
        CP_COMMIT();                                                           \
    } while (0)

    ISSUE_STAGE(0);

    // ---- register-compacted ldmatrix addressing ----
    const uint32_t xA = ((uint32_t)(lane & 7)) << 4;
    const uint32_t chunkA = ((uint32_t)(lane >> 4)) * 16u;
    const uint32_t aBase = sbase + (uint32_t)(wm * 64 + (lane & 15)) * 128u;  // +mi*2048
    const uint32_t chunkB = ((uint32_t)((lane >> 3) & 1)) * 16u;
    const uint32_t bBase = sbase + (uint32_t)(BM * BK * 2) +
        (uint32_t)(wn * 64 + ((lane >> 4) & 1) * 8 + (lane & 7)) * 128u;      // +np*2048

    uint32_t acc[4][8][2];   // f16x2 accumulators (64 regs)
#pragma unroll
    for (int mi = 0; mi < 4; mi++)
#pragma unroll
        for (int ni = 0; ni < 8; ni++) {
            acc[mi][ni][0] = 0u;
            acc[mi][ni][1] = 0u;
        }

    // ---- mainloop: wait stage i, sync, prefetch stage i+1, compute ----
#pragma unroll 1
    for (int i = 0; i < KITERS; i++) {
        asm volatile("cp.async.wait_group 0;" ::: "memory");
        __syncthreads();
        if (i + 1 < KITERS) ISSUE_STAGE(i + 1);

        const uint32_t sb = (uint32_t)(i & 1) * STAGE_BYTES;
#pragma unroll
        for (int kk = 0; kk < 4; kk++) {
            const uint32_t kkb = (uint32_t)kk * 32u;
            const uint32_t offA = sb + ((kkb | chunkA) ^ xA);
            const uint32_t offB = sb + ((kkb | chunkB) ^ xA);
            uint32_t a[4][4], b[4][4];
#pragma unroll
            for (int mi = 0; mi < 4; mi++)
                LDSM_X4(a[mi][0], a[mi][1], a[mi][2], a[mi][3],
                        aBase + (uint32_t)(mi * 2048) + offA);
#pragma unroll
            for (int np = 0; np < 4; np++)
                LDSM_X4(b[np][0], b[np][1], b[np][2], b[np][3],
                        bBase + (uint32_t)(np * 2048) + offB);
#pragma unroll
            for (int mi = 0; mi < 4; mi++)
#pragma unroll
                for (int ni = 0; ni < 8; ni++)
                    MMAF16(acc[mi][ni],
                           a[mi][0], a[mi][1], a[mi][2], a[mi][3],
                           b[ni >> 1][(ni & 1) * 2],
                           b[ni >> 1][(ni & 1) * 2 + 1]);
        }
    }

    // ---- epilogue: promote, exp, positive capture, row/col partials ----
    float vr[4][2];
    float cv[8][2];
#pragma unroll
    for (int i = 0; i < 4; i++) { vr[i][0] = vr[i][1] = 0.f; }
#pragma unroll
    for (int i = 0; i < 8; i++) { cv[i][0] = cv[i][1] = 0.f; }

#pragma unroll
    for (int mi = 0; mi < 4; mi++)
#pragma unroll
        for (int ni = 0; ni < 8; ni++)
#pragma unroll
            for (int h = 0; h < 2; h++) {
                float2 f = __half22float2(*(__half2*)&acc[mi][ni][h]);
                int rowg = r0 + wm * 64 + mi * 16 + h * 8 + (lane >> 2);
                int colb = c0 + wn * 64 + ni * 8 + (lane & 3) * 2;
                float v0 = __expf(f.x * 10.0f);
                float v1 = __expf(f.y * 10.0f);
                vr[mi][h] += v0 + v1;
                cv[ni][0] += v0;
                cv[ni][1] += v1;
                if (colb == rowg + BHALF) g_pos[rowg] = v0;
                if (colb + 1 == rowg + BHALF) g_pos[rowg] = v1;
            }
#pragma unroll
    for (int mi = 0; mi < 4; mi++)
#pragma unroll
        for (int h = 0; h < 2; h++) {
            float v = vr[mi][h];
            v += __shfl_xor_sync(0xFFFFFFFFu, v, 1);
            v += __shfl_xor_sync(0xFFFFFFFFu, v, 2);
            vr[mi][h] = v;
        }
#pragma unroll
    for (int ni = 0; ni < 8; ni++)
#pragma unroll
        for (int b = 0; b < 2; b++) {
            float v = cv[ni][b];
            v += __shfl_xor_sync(0xFFFFFFFFu, v, 4);
            v += __shfl_xor_sync(0xFFFFFFFFu, v, 8);
            v += __shfl_xor_sync(0xFFFFFFFFu, v, 16);
            cv[ni][b] = v;
        }

    __syncthreads();
    float* redr = (float*)smem;          // [2 wn][128 rows]
    float* redc = (float*)smem + 256;    // [2 wm][128 cols]
    if ((lane & 3) == 0) {
#pragma unroll
        for (int mi = 0; mi < 4; mi++)
#pragma unroll
            for (int h = 0; h < 2; h++)
                redr[wn * 128 + wm * 64 + mi * 16 + h * 8 + (lane >> 2)] = vr[mi][h];
    }
    if (lane < 4) {
#pragma unroll
        for (int ni = 0; ni < 8; ni++)
#pragma unroll
            for (int b = 0; b < 2; b++)
                redc[wm * 128 + wn * 64 + ni * 8 + lane * 2 + b] = cv[ni][b];
    }
    __syncthreads();
    {
        float t = redr[tid] + redr[128 + tid];
        g_rs[((size_t)(r0 + tid)) * NB + bn] = t;
        if (bm != bn) {
            float u = redc[tid] + redc[128 + tid];
            g_rs[((size_t)(c0 + tid)) * NB + bm] = u;
        }
    }
}

// ---------------------------------------------------------------------------
// Kernel 3: per-128-row partial loss sums; last block finalizes the scalar.
// (identical to R12)
// ---------------------------------------------------------------------------
__global__ void loss_kernel(float* __restrict__ out) {
    int r = blockIdx.x * 128 + threadIdx.x;
    const float4* p4 = (const float4*)&g_rs[(size_t)r * NB];
    float tot = 0.f;
#pragma unroll
    for (int i = 0; i < NB / 4; i++) {
        float4 q = p4[i];
        tot += (q.x + q.y) + (q.z + q.w);
    }
    float p = g_pos[r & (BHALF - 1)];
    float s = logf(tot - p) - logf(p);
#pragma unroll
    for (int o = 16; o; o >>= 1) s += __shfl_xor_sync(0xFFFFFFFFu, s, o);
    __shared__ float ws[4];
    __shared__ int is_last;
    if ((threadIdx.x & 31) == 0) ws[threadIdx.x >> 5] = s;
    __syncthreads();
    if (threadIdx.x == 0) {
        g_part[blockIdx.x] = ws[0] + ws[1] + ws[2] + ws[3];
        __threadfence();
        is_last = (atomicAdd(&g_cnt, 1) == 63) ? 1 : 0;
        if (is_last) g_cnt = 0;   // reset for next graph replay
    }
    __syncthreads();
    if (is_last && threadIdx.x < 64) {
        float v = g_part[threadIdx.x];
#pragma unroll
        for (int o = 16; o; o >>= 1) v += __shfl_xor_sync(0xFFFFFFFFu, v, o);
        __shared__ float h2[2];
        if ((threadIdx.x & 31) == 0) h2[threadIdx.x >> 5] = v;
        __syncwarp();
        __syncthreads();
        if (threadIdx.x == 0)
            out[0] = (h2[0] + h2[1]) / ((float)NROWS * (float)BHALF);
    }
}

extern "C" void kernel_launch(void* const* d_in, const int* in_sizes, int n_in,
                              void* d_out, int out_size) {
    const float* z1 = (const float*)d_in[0];
    const float* z2 = (const float*)d_in[1];
    (void)in_sizes; (void)n_in; (void)out_size;

    cudaFuncSetAttribute(gemm_kernel, cudaFuncAttributeMaxDynamicSharedMemorySize,
                         SMEM_TOTAL);

    normalize_kernel<<<NROWS / 16, 512>>>(z1, z2);
    gemm_kernel<<<NPAIRS, 128, SMEM_TOTAL>>>();
    loss_kernel<<<64, 128>>>((float*)d_out);
}